// round 12
// baseline (speedup 1.0000x reference)
#include <cuda_runtime.h>
#include <cuda_bf16.h>

#define L 2048
#define LMASK 2047
#define LSHIFT 11
#define PAIRMASK 0x5A48u
#define CAP 192            // finish smem-cache capacity
#define NB 120             // solver blocks (1/SM at this smem size; all resident)

// ---------------- device scratch ----------------
__device__ float d_S[(size_t)L * L];          // masked symmetric matrix
__device__ unsigned long long d_best[L];      // per-vertex best edge priority (cached, lazy)
__device__ int d_cls[L];
__device__ int d_list[2][L];                  // ping-pong survivor lists (global ids, ascending)
__device__ int d_nL[2];
__device__ int d_resc[L];                     // rescan subset of survivors
__device__ int d_nResc;
__device__ unsigned g_count = 0;              // grid barrier (self-resetting)
__device__ unsigned g_sense = 0;              // grid barrier generation (monotonic)

// priority: value desc, flat index (i*L+j, i<j) asc — exact stable-sort tiebreak
__device__ __forceinline__ unsigned long long pack_g(float s, int i, int j) {
    unsigned k = (unsigned)(i * L + j);
    return ((unsigned long long)__float_as_uint(s) << 32) | (unsigned long long)(~k);
}
__device__ __forceinline__ unsigned long long warp_max(unsigned long long m) {
    #pragma unroll
    for (int o = 16; o; o >>= 1) {
        unsigned long long q = __shfl_xor_sync(0xFFFFFFFFu, m, o);
        if (q > m) m = q;
    }
    return m;
}
// triangular block map: k -> (bi, bj) with bi <= bj
__device__ __forceinline__ void tri_map(int k, int& bi, int& bj) {
    int b = (int)((__fsqrt_rn(8.0f * (float)k + 1.0f) - 1.0f) * 0.5f);
    while (b * (b + 1) / 2 > k) b--;
    while ((b + 1) * (b + 2) / 2 <= k) b++;
    bj = b;
    bi = k - b * (b + 1) / 2;
}
// grid barrier: all NB blocks arrive; count self-resets via atomicInc wrap.
// gen is tracked in thread 0's register (seeded from g_sense at kernel entry,
// which is race-free: no bump can occur before all blocks arrive at barrier 1).
__device__ __forceinline__ void gsync(unsigned& gen) {
    __syncthreads();
    if (threadIdx.x == 0) {
        __threadfence();
        unsigned old = atomicInc(&g_count, NB - 1);
        if (old == NB - 1) {
            atomicAdd(&g_sense, 1);
        } else {
            while (atomicAdd(&g_sense, 0) == gen) __nanosleep(64);
        }
        gen++;
        __threadfence();
    }
    __syncthreads();
}

// ---------------- K1: classes + clear best ----------------
__global__ void kern_cls(const float* __restrict__ feat) {
    int i = blockIdx.x * blockDim.x + threadIdx.x;
    if (i >= L) return;
    float f0 = feat[(size_t)i * L];
    float f1 = feat[(size_t)L * L + (size_t)i * L];
    float f2 = feat[2 * (size_t)L * L + (size_t)i * L];
    float f3 = feat[3 * (size_t)L * L + (size_t)i * L];
    int c = 0; float m = f0;
    if (f1 > m) { m = f1; c = 1; }
    if (f2 > m) { m = f2; c = 2; }
    if (f3 > m) { m = f3; c = 3; }
    d_cls[i] = c;
    d_best[i] = 0ULL;                       // re-zero every replay (lazy cache persists)
}

// ---------------- K2: masked symmetric S + round-1 best + zero output ----------------
__global__ void kern_build(const float* __restrict__ con, float* __restrict__ out) {
    int bi, bj; tri_map(blockIdx.x, bi, bj);      // bi <= bj

    __shared__ float sB[32][33];
    __shared__ int clsR[32], clsC[32];

    int tx = threadIdx.x, ty = threadIdx.y;
    int i = bi * 32 + ty;
    int j = bj * 32 + tx;

    if (ty == 0) { clsR[tx] = d_cls[bi * 32 + tx]; clsC[tx] = d_cls[bj * 32 + tx]; }

    float a = con[(size_t)i * L + j];
    sB[ty][tx] = con[(size_t)(bj * 32 + ty) * L + (bi * 32 + tx)];
    __syncthreads();

    float b = sB[tx][ty];          // con[j][i]
    float v = 0.5f * (a + b);
    int d = j - i;
    bool band = (d >= 4) || (d <= -4);
    bool pm = (PAIRMASK >> ((clsR[ty] << 2) | clsC[tx])) & 1u;
    float s = (band && pm) ? v : 0.0f;

    out[(size_t)i * L + j] = 0.0f;
    out[(size_t)(bj * 32 + ty) * L + (bi * 32 + tx)] = 0.0f;

    d_S[(size_t)i * L + j] = s;                   // direct tile, coalesced

    unsigned long long p = (s > 0.0f && j > i) ? pack_g(s, i, j) : 0ULL;
    unsigned long long m = warp_max(p);
    if (tx == 0 && m) atomicMax(&d_best[i], m);

    __syncthreads();
    sB[ty][tx] = s;
    __syncthreads();
    float s2 = sB[tx][ty];                 // pair (i2 = bi*32+tx, j2 = bj*32+ty)
    int i2 = bi * 32 + tx, j2 = bj * 32 + ty;
    d_S[(size_t)j2 * L + i2] = s2;                // mirrored tile, coalesced over tx
    unsigned long long p2 = (s2 > 0.0f && j2 > i2) ? pack_g(s2, i2, j2) : 0ULL;
    unsigned long long cm = warp_max(p2);
    if (tx == 0 && cm) atomicMax(&d_best[j2], cm);
}

// ---------------- K3: persistent solver — all rounds in one kernel ----------------
__global__ void __launch_bounds__(1024, 1) kern_solve(float* __restrict__ out) {
    extern __shared__ float sC[];              // CAP*CAP floats (dynamic; block 0's finish)
    __shared__ int sList[L];
    __shared__ int sTmp[L];
    __shared__ short sPos[L];
    __shared__ unsigned long long sBest[L];
    __shared__ int wsum[32];
    __shared__ int sTotal;

    int t = threadIdx.x, lane = t & 31, wid = t >> 5;
    unsigned gen = 0;
    if (t == 0) gen = atomicAdd(&g_sense, 0);  // entry read: race-free (see gsync)

    int cur = -1, nxt = 0;
    int n = L;

    while (true) {
        // ===== take + classify: block 0 only =====
        if (blockIdx.x == 0) {
            int f[2]; int vv[2];
            #pragma unroll
            for (int r = 0; r < 2; r++) {
                int idx = 2 * t + r;
                int fl = 0, v = -1;
                if (idx < n) {
                    v = (cur < 0) ? idx : __ldcg(&d_list[cur][idx]);
                    unsigned long long b = __ldcg(&d_best[v]);
                    if (b) {
                        unsigned k = ~((unsigned)b);
                        int i = (int)(k >> LSHIFT), j = (int)(k & LMASK);
                        int u = (v == i) ? j : i;
                        unsigned long long bu = __ldcg(&d_best[u]);
                        if (bu == b) {
                            if (v == i) {   // taken: write once per pair
                                float val = __uint_as_float((unsigned)(b >> 32));
                                out[i * L + j] = val;
                                out[j * L + i] = val;
                            }
                        } else {
                            // survivor; rescan iff best partner u was taken
                            unsigned k2 = ~((unsigned)bu);
                            int i2 = (int)(k2 >> LSHIFT), j2 = (int)(k2 & LMASK);
                            int w = (u == i2) ? j2 : i2;
                            fl = (__ldcg(&d_best[w]) == bu) ? 2 : 1;
                        }
                    }
                }
                f[r] = fl; vv[r] = v;
            }
            // scan 1: survivors (fl >= 1) -> d_list[nxt]
            {
                int g0 = (f[0] >= 1), g1 = (f[1] >= 1);
                int sum = g0 + g1;
                int x = sum;
                #pragma unroll
                for (int o = 1; o < 32; o <<= 1) { int y = __shfl_up_sync(0xFFFFFFFFu, x, o); if (lane >= o) x += y; }
                if (lane == 31) wsum[wid] = x;
                __syncthreads();
                if (wid == 0) {
                    int z = wsum[lane];
                    #pragma unroll
                    for (int o = 1; o < 32; o <<= 1) { int y = __shfl_up_sync(0xFFFFFFFFu, z, o); if (lane >= o) z += y; }
                    wsum[lane] = z;
                    if (lane == 31) sTotal = z;
                }
                __syncthreads();
                int ex = (wid ? wsum[wid - 1] : 0) + x - sum;
                if (g0) d_list[nxt][ex] = vv[0];
                if (g1) d_list[nxt][ex + g0] = vv[1];
                if (t == 0) d_nL[nxt] = sTotal;
            }
            __syncthreads();
            // scan 2: rescan subset (fl == 2) -> d_resc
            {
                int g0 = (f[0] == 2), g1 = (f[1] == 2);
                int sum = g0 + g1;
                int x = sum;
                #pragma unroll
                for (int o = 1; o < 32; o <<= 1) { int y = __shfl_up_sync(0xFFFFFFFFu, x, o); if (lane >= o) x += y; }
                if (lane == 31) wsum[wid] = x;
                __syncthreads();
                if (wid == 0) {
                    int z = wsum[lane];
                    #pragma unroll
                    for (int o = 1; o < 32; o <<= 1) { int y = __shfl_up_sync(0xFFFFFFFFu, z, o); if (lane >= o) z += y; }
                    wsum[lane] = z;
                    if (lane == 31) sTotal = z;
                }
                __syncthreads();
                int ex = (wid ? wsum[wid - 1] : 0) + x - sum;
                if (g0) d_resc[ex] = vv[0];
                if (g1) d_resc[ex + g0] = vv[1];
                if (t == 0) d_nResc = sTotal;
            }
        }
        gsync(gen);

        n = __ldcg(&d_nL[nxt]);
        int m0 = __ldcg(&d_nResc);

        // ===== best over rescan rows: all blocks =====
        if (m0 > 0 && n > 0) {
            for (int x = t; x < n; x += 1024) sList[x] = __ldcg(&d_list[nxt][x]);
            __syncthreads();
            int start = blockIdx.x * 32 + wid;
            int stride = NB * 32;
            for (int a = start; a < m0; a += stride) {
                int v = __ldcg(&d_resc[a]);
                const float* __restrict__ row = d_S + (size_t)v * L;
                unsigned long long m = 0ULL;
                #pragma unroll 4
                for (int l = lane; l < n; l += 32) {
                    int u = sList[l];
                    float s = __ldg(&row[u]);
                    if (s > 0.0f) {
                        unsigned long long p = (v < u) ? pack_g(s, v, u) : pack_g(s, u, v);
                        if (p > m) m = p;
                    }
                }
                m = warp_max(m);
                if (lane == 0) d_best[v] = m;
            }
        }
        gsync(gen);

        cur = nxt; nxt ^= 1;
        if (n <= CAP) break;
    }

    if (blockIdx.x != 0 || n == 0) return;

    // ===== finish: block 0, smem-cached S submatrix (n <= CAP) =====
    for (int x = t; x < n; x += 1024) {
        int v = __ldcg(&d_list[cur][x]);
        sList[x] = v;
        sPos[v] = (short)x;
        sBest[v] = __ldcg(&d_best[v]);
    }
    __syncthreads();
    int ne = n;
    for (int idx = t; idx < ne * ne; idx += 1024) {
        int ai = idx / ne, bi2 = idx - ai * ne;
        sC[idx] = __ldg(&d_S[(size_t)sList[ai] * L + sList[bi2]]);
    }
    __syncthreads();

    while (n > 0) {
        // ---- take ----
        int f[2]; int vv[2];
        #pragma unroll
        for (int r = 0; r < 2; r++) {
            int idx = 2 * t + r;
            int fl = 0, v = -1;
            if (idx < n) {
                v = sList[idx];
                unsigned long long b = sBest[v];
                if (b) {
                    unsigned k = ~((unsigned)b);
                    int i = (int)(k >> LSHIFT), j = (int)(k & LMASK);
                    int u = (v == i) ? j : i;
                    if (sBest[u] == b) {
                        if (v == i) {
                            float val = __uint_as_float((unsigned)(b >> 32));
                            out[i * L + j] = val;
                            out[j * L + i] = val;
                        }
                    } else fl = 1;
                }
            }
            f[r] = fl; vv[r] = v;
        }

        int sum = f[0] + f[1];
        int x = sum;
        #pragma unroll
        for (int o = 1; o < 32; o <<= 1) { int y = __shfl_up_sync(0xFFFFFFFFu, x, o); if (lane >= o) x += y; }
        if (lane == 31) wsum[wid] = x;
        __syncthreads();
        if (wid == 0) {
            int z = wsum[lane];
            #pragma unroll
            for (int o = 1; o < 32; o <<= 1) { int y = __shfl_up_sync(0xFFFFFFFFu, z, o); if (lane >= o) z += y; }
            wsum[lane] = z;
            if (lane == 31) sTotal = z;
        }
        __syncthreads();
        int ex = (wid ? wsum[wid - 1] : 0) + x - sum;
        if (f[0]) sTmp[ex] = vv[0];
        if (f[1]) sTmp[ex + f[0]] = vv[1];
        __syncthreads();
        int nn = sTotal;
        for (int x2 = t; x2 < nn; x2 += 1024) sList[x2] = sTmp[x2];
        __syncthreads();
        n = nn;
        if (n == 0) break;

        // ---- best (smem-resident) ----
        for (int ai = wid; ai < n; ai += 32) {
            int v = sList[ai];
            int pa = sPos[v];
            unsigned long long m = 0ULL;
            for (int li = lane; li < n; li += 32) {
                int u = sList[li];
                float s = sC[pa * ne + sPos[u]];
                if (s > 0.0f) {
                    unsigned long long p = (v < u) ? pack_g(s, v, u) : pack_g(s, u, v);
                    if (p > m) m = p;
                }
            }
            m = warp_max(m);
            if (lane == 0) sBest[v] = m;
        }
        __syncthreads();
    }
}

// ---------------- launch ----------------
extern "C" void kernel_launch(void* const* d_in, const int* in_sizes, int n_in,
                              void* d_out, int out_size) {
    const float* con  = (const float*)d_in[0];
    const float* feat = (const float*)d_in[1];
    if (n_in >= 2 && in_sizes[0] > in_sizes[1]) {
        const float* tmp = con; con = feat; feat = tmp;
    }
    float* out = (float*)d_out;

    static int smemSet = 0;
    if (!smemSet) {
        cudaFuncSetAttribute(kern_solve, cudaFuncAttributeMaxDynamicSharedMemorySize,
                             CAP * CAP * (int)sizeof(float));
        smemSet = 1;
    }

    const int TRI32 = (L / 32) * (L / 32 + 1) / 2;   // 2080
    dim3 tb(32, 32);

    kern_cls<<<8, 256>>>(feat);
    kern_build<<<TRI32, tb>>>(con, out);           // S + round-1 best + output zeroing
    kern_solve<<<NB, 1024, CAP * CAP * (int)sizeof(float)>>>(out);  // all rounds + tail
}

// round 13
// speedup vs baseline: 1.1686x; 1.1686x over previous
#include <cuda_runtime.h>
#include <cuda_bf16.h>

#define L 2048
#define LMASK 2047
#define LSHIFT 11
#define PAIRMASK 0x5A48u
#define CAP 192            // finish smem-cache capacity

// ---------------- device scratch ----------------
__device__ float d_S[(size_t)L * L];          // masked symmetric matrix
__device__ unsigned long long d_best[L];      // per-vertex best edge priority (cached, lazy)
__device__ int d_cls[L];
__device__ int d_list[2][L];                  // ping-pong survivor lists (global ids, ascending)
__device__ int d_nL[2];
__device__ int d_resc[L];                     // rescan subset of survivors
__device__ int d_nResc;

// priority: value desc, flat index (i*L+j, i<j) asc — exact stable-sort tiebreak
__device__ __forceinline__ unsigned long long pack_g(float s, int i, int j) {
    unsigned k = (unsigned)(i * L + j);
    return ((unsigned long long)__float_as_uint(s) << 32) | (unsigned long long)(~k);
}
__device__ __forceinline__ unsigned long long warp_max(unsigned long long m) {
    #pragma unroll
    for (int o = 16; o; o >>= 1) {
        unsigned long long q = __shfl_xor_sync(0xFFFFFFFFu, m, o);
        if (q > m) m = q;
    }
    return m;
}

// ---------------- K1: classes + clear best ----------------
__global__ void kern_cls(const float* __restrict__ feat) {
    int i = blockIdx.x * blockDim.x + threadIdx.x;
    if (i >= L) return;
    float f0 = __ldg(&feat[(size_t)i * L]);
    float f1 = __ldg(&feat[(size_t)L * L + (size_t)i * L]);
    float f2 = __ldg(&feat[2 * (size_t)L * L + (size_t)i * L]);
    float f3 = __ldg(&feat[3 * (size_t)L * L + (size_t)i * L]);
    int c = 0; float m = f0;
    if (f1 > m) { m = f1; c = 1; }
    if (f2 > m) { m = f2; c = 2; }
    if (f3 > m) { m = f3; c = 3; }
    d_cls[i] = c;
    d_best[i] = 0ULL;                       // re-zero every replay (lazy cache persists)
}

// ---------------- K2: masked symmetric S + round-1 best + zero output ----------------
// 32-row x 128-col tiles, float4 everywhere. Grid (bj=16, bi=64); tiles fully below
// the diagonal are skipped — their S/out entries are written by the mirror phase of
// the transposed tile. Diagonal-overlap double-writes are benign (same values).
__global__ void kern_build(const float* __restrict__ con, float* __restrict__ out) {
    int bj = blockIdx.x;           // col tile: cols [bj*128, bj*128+128)
    int bi = blockIdx.y;           // row tile: rows [bi*32, bi*32+32)
    if (4 * bj + 3 < bi) return;   // tile entirely below diagonal

    __shared__ float sT[128][33];  // holds con[j][i] during compute, then s for mirror
    __shared__ int clsR[32];
    __shared__ unsigned char clsC[128];

    int tx = threadIdx.x, ty = threadIdx.y;
    int t = ty * 32 + tx;

    if (t < 32) clsR[t] = d_cls[bi * 32 + t];
    else if (t < 160) clsC[t - 32] = (unsigned char)d_cls[bj * 128 + (t - 32)];

    const float4* __restrict__ con4 = (const float4*)con;
    float4* __restrict__ out4 = (float4*)out;
    float4* __restrict__ S4 = (float4*)d_S;

    // direct tile: con[i][jbase..jbase+3]
    int i = bi * 32 + ty;
    float4 a = __ldg(&con4[(size_t)i * (L / 4) + bj * 32 + tx]);

    // mirrored source: con[bj*128 + r][bi*32 .. +32), one float4 per thread
    {
        int r = t >> 3, c4 = t & 7;
        float4 b4 = __ldg(&con4[(size_t)(bj * 128 + r) * (L / 4) + bi * 8 + c4]);
        sT[r][c4 * 4 + 0] = b4.x;
        sT[r][c4 * 4 + 1] = b4.y;
        sT[r][c4 * 4 + 2] = b4.z;
        sT[r][c4 * 4 + 3] = b4.w;
    }
    __syncthreads();

    // compute s for 4 elements; direct S write; fused out zeroing; row-best
    float sv[4];
    unsigned long long m = 0ULL;
    int cr = clsR[ty];
    #pragma unroll
    for (int k = 0; k < 4; k++) {
        int jj = tx * 4 + k;
        int j = bj * 128 + jj;
        float av = (k == 0) ? a.x : (k == 1) ? a.y : (k == 2) ? a.z : a.w;
        float v = 0.5f * (av + sT[jj][ty]);
        int d = j - i;
        bool band = (d >= 4) || (d <= -4);
        bool pm = (PAIRMASK >> ((cr << 2) | clsC[jj])) & 1u;
        float s = (band && pm) ? v : 0.0f;
        sv[k] = s;
        if (s > 0.0f && j > i) {
            unsigned long long p = pack_g(s, i, j);
            if (p > m) m = p;
        }
    }
    S4[(size_t)i * (L / 4) + bj * 32 + tx] = make_float4(sv[0], sv[1], sv[2], sv[3]);
    out4[(size_t)i * (L / 4) + bj * 32 + tx] = make_float4(0.f, 0.f, 0.f, 0.f);
    m = warp_max(m);
    if (tx == 0 && m) atomicMax(&d_best[i], m);

    // stage s into sT for the mirror phase
    __syncthreads();
    #pragma unroll
    for (int k = 0; k < 4; k++) sT[tx * 4 + k][ty] = sv[k];
    __syncthreads();

    // mirror: S[j][i] + out zero + column best. Warp ty handles rows jj = ty*4..+3.
    #pragma unroll
    for (int rr = 0; rr < 4; rr++) {
        int jj = ty * 4 + rr;
        int j = bj * 128 + jj;
        float s2 = sT[jj][tx];                 // value for pair (i2 = bi*32+tx, j)
        d_S[(size_t)j * L + bi * 32 + tx] = s2;        // coalesced over tx
        int i2 = bi * 32 + tx;
        unsigned long long p2 = (s2 > 0.0f && j > i2) ? pack_g(s2, i2, j) : 0ULL;
        unsigned long long cm = warp_max(p2);
        if (tx == 0 && cm) atomicMax(&d_best[j], cm);
    }
    // mirrored out zero (float4): rows bj*128.., cols bi*32..+32
    {
        int r = t >> 3, c4 = t & 7;
        out4[(size_t)(bj * 128 + r) * (L / 4) + bi * 8 + c4] = make_float4(0.f, 0.f, 0.f, 0.f);
    }
}

// ---------------- K3: take + classify (1 block; srcSel<0 = all L vertices) ----------------
// Emits survivor list (dstSel) AND rescan subset (survivors whose best partner was taken).
__global__ void kern_take(int srcSel, int dstSel, float* __restrict__ out) {
    __shared__ int wsum[32];
    __shared__ int sTotal;
    int t = threadIdx.x;
    int lane = t & 31, wid = t >> 5;
    int n = (srcSel < 0) ? L : d_nL[srcSel];
    const int* lst = (srcSel < 0) ? 0 : d_list[srcSel];

    int f[2];   // 0=dead/taken, 1=survive cached, 2=survive rescan
    int vv[2];
    #pragma unroll
    for (int r = 0; r < 2; r++) {
        int idx = 2 * t + r;
        int fl = 0, v = -1;
        if (idx < n) {
            v = lst ? lst[idx] : idx;
            unsigned long long b = d_best[v];
            if (b) {
                unsigned k = ~((unsigned)b);
                int i = (int)(k >> LSHIFT), j = (int)(k & LMASK);
                int u = (v == i) ? j : i;
                unsigned long long bu = d_best[u];
                if (bu == b) {
                    if (v == i) {   // taken: write once per pair
                        float val = __uint_as_float((unsigned)(b >> 32));
                        out[i * L + j] = val;
                        out[j * L + i] = val;
                    }
                } else {
                    unsigned k2 = ~((unsigned)bu);
                    int i2 = (int)(k2 >> LSHIFT), j2 = (int)(k2 & LMASK);
                    int w = (u == i2) ? j2 : i2;
                    fl = (d_best[w] == bu) ? 2 : 1;    // rescan iff u was taken
                }
            }
        }
        f[r] = fl; vv[r] = v;
    }

    // scan 1: survivors (fl >= 1) -> d_list[dstSel]
    {
        int g0 = (f[0] >= 1), g1 = (f[1] >= 1);
        int sum = g0 + g1;
        int x = sum;
        #pragma unroll
        for (int o = 1; o < 32; o <<= 1) { int y = __shfl_up_sync(0xFFFFFFFFu, x, o); if (lane >= o) x += y; }
        if (lane == 31) wsum[wid] = x;
        __syncthreads();
        if (wid == 0) {
            int z = wsum[lane];
            #pragma unroll
            for (int o = 1; o < 32; o <<= 1) { int y = __shfl_up_sync(0xFFFFFFFFu, z, o); if (lane >= o) z += y; }
            wsum[lane] = z;
            if (lane == 31) sTotal = z;
        }
        __syncthreads();
        int ex = (wid ? wsum[wid - 1] : 0) + x - sum;
        if (g0) d_list[dstSel][ex] = vv[0];
        if (g1) d_list[dstSel][ex + g0] = vv[1];
        if (t == 0) d_nL[dstSel] = sTotal;
    }
    __syncthreads();

    // scan 2: rescan subset (fl == 2) -> d_resc
    {
        int g0 = (f[0] == 2), g1 = (f[1] == 2);
        int sum = g0 + g1;
        int x = sum;
        #pragma unroll
        for (int o = 1; o < 32; o <<= 1) { int y = __shfl_up_sync(0xFFFFFFFFu, x, o); if (lane >= o) x += y; }
        if (lane == 31) wsum[wid] = x;
        __syncthreads();
        if (wid == 0) {
            int z = wsum[lane];
            #pragma unroll
            for (int o = 1; o < 32; o <<= 1) { int y = __shfl_up_sync(0xFFFFFFFFu, z, o); if (lane >= o) z += y; }
            wsum[lane] = z;
            if (lane == 31) sTotal = z;
        }
        __syncthreads();
        int ex = (wid ? wsum[wid - 1] : 0) + x - sum;
        if (g0) d_resc[ex] = vv[0];
        if (g1) d_resc[ex + g0] = vv[1];
        if (t == 0) d_nResc = sTotal;
    }
}

// ---------------- K4: best — rescan rows only, gathered with unroll-4 MLP ----------------
__global__ void kern_bestG(int sel) {
    __shared__ int sAct[L];
    int n = d_nL[sel];
    int m0 = d_nResc;
    if (m0 == 0 || n == 0) return;
    const int* lst = d_list[sel];
    for (int t = threadIdx.x; t < n; t += blockDim.x) sAct[t] = lst[t];
    __syncthreads();

    int lane = threadIdx.x & 31;
    int wid = threadIdx.x >> 5;                       // 0..7
    int start = blockIdx.x * 8 + wid;                 // rows interleaved over blocks
    int stride = gridDim.x * 8;

    for (int a = start; a < m0; a += stride) {
        int v = d_resc[a];
        const float* __restrict__ row = d_S + (size_t)v * L;
        unsigned long long m = 0ULL;
        #pragma unroll 4
        for (int l = lane; l < n; l += 32) {
            int u = sAct[l];
            float s = __ldg(&row[u]);
            if (s > 0.0f) {
                unsigned long long p = (v < u) ? pack_g(s, v, u) : pack_g(s, u, v);
                if (p > m) m = p;
            }
        }
        m = warp_max(m);
        if (lane == 0) d_best[v] = m;
    }
}

// ---------------- K5: persistent tail with smem-cached S submatrix ----------------
__global__ void kern_finish(int sel, float* __restrict__ out) {
    extern __shared__ float sC[];              // CAP*CAP floats (dynamic)
    __shared__ int sCur[L];
    __shared__ int sTmp[L];
    __shared__ short sPos[L];
    __shared__ unsigned long long sBest[L];
    __shared__ int wsum[32];
    __shared__ int sTotal;

    int t = threadIdx.x, lane = t & 31, wid = t >> 5;
    int n = d_nL[sel];
    if (n == 0) return;

    for (int x = t; x < n; x += 1024) {
        int v = d_list[sel][x];
        sCur[x] = v;
        sPos[v] = (short)x;
        sBest[v] = d_best[v];
    }
    __syncthreads();

    bool useC = (n <= CAP);
    int ne = n;
    if (useC) {
        for (int idx = t; idx < ne * ne; idx += 1024) {
            int ai = idx / ne, bi2 = idx - ai * ne;
            sC[idx] = d_S[(size_t)sCur[ai] * L + sCur[bi2]];
        }
        __syncthreads();
    }

    while (n > 0) {
        // ---- take ----
        int f[2]; int vv[2];
        #pragma unroll
        for (int r = 0; r < 2; r++) {
            int idx = 2 * t + r;
            int fl = 0, v = -1;
            if (idx < n) {
                v = sCur[idx];
                unsigned long long b = sBest[v];
                if (b) {
                    unsigned k = ~((unsigned)b);
                    int i = (int)(k >> LSHIFT), j = (int)(k & LMASK);
                    int u = (v == i) ? j : i;
                    if (sBest[u] == b) {
                        if (v == i) {
                            float val = __uint_as_float((unsigned)(b >> 32));
                            out[i * L + j] = val;
                            out[j * L + i] = val;
                        }
                    } else fl = 1;
                }
            }
            f[r] = fl; vv[r] = v;
        }

        int sum = f[0] + f[1];
        int x = sum;
        #pragma unroll
        for (int o = 1; o < 32; o <<= 1) { int y = __shfl_up_sync(0xFFFFFFFFu, x, o); if (lane >= o) x += y; }
        if (lane == 31) wsum[wid] = x;
        __syncthreads();
        if (wid == 0) {
            int z = wsum[lane];
            #pragma unroll
            for (int o = 1; o < 32; o <<= 1) { int y = __shfl_up_sync(0xFFFFFFFFu, z, o); if (lane >= o) z += y; }
            wsum[lane] = z;
            if (lane == 31) sTotal = z;
        }
        __syncthreads();
        int ex = (wid ? wsum[wid - 1] : 0) + x - sum;
        if (f[0]) sTmp[ex] = vv[0];
        if (f[1]) sTmp[ex + f[0]] = vv[1];
        __syncthreads();
        int nn = sTotal;
        for (int x2 = t; x2 < nn; x2 += 1024) sCur[x2] = sTmp[x2];
        __syncthreads();
        n = nn;
        if (n == 0) break;

        // ---- best ----
        for (int ai = wid; ai < n; ai += 32) {
            int v = sCur[ai];
            int pa = useC ? sPos[v] : 0;
            unsigned long long m = 0ULL;
            for (int li = lane; li < n; li += 32) {
                int u = sCur[li];
                float s = useC ? sC[pa * ne + sPos[u]]
                               : d_S[(size_t)v * L + u];
                if (s > 0.0f) {
                    unsigned long long p = (v < u) ? pack_g(s, v, u) : pack_g(s, u, v);
                    if (p > m) m = p;
                }
            }
            m = warp_max(m);
            if (lane == 0) sBest[v] = m;
        }
        __syncthreads();
    }
}

// ---------------- launch ----------------
extern "C" void kernel_launch(void* const* d_in, const int* in_sizes, int n_in,
                              void* d_out, int out_size) {
    const float* con  = (const float*)d_in[0];
    const float* feat = (const float*)d_in[1];
    if (n_in >= 2 && in_sizes[0] > in_sizes[1]) {
        const float* tmp = con; con = feat; feat = tmp;
    }
    float* out = (float*)d_out;

    static int smemSet = 0;
    if (!smemSet) {
        cudaFuncSetAttribute(kern_finish, cudaFuncAttributeMaxDynamicSharedMemorySize,
                             CAP * CAP * (int)sizeof(float));
        smemSet = 1;
    }

    kern_cls<<<8, 256>>>(feat);

    dim3 gb(L / 128, L / 32), tb(32, 32);          // (16, 64) tiles
    kern_build<<<gb, tb>>>(con, out);              // S + round-1 best + output zeroing

    kern_take<<<1, 1024>>>(-1, 0, out);            // take1 -> list0 + rescan set
    kern_bestG<<<128, 256>>>(0);                   // best2 (rescan rows only)
    kern_take<<<1, 1024>>>(0, 1, out);             // take2
    kern_bestG<<<128, 256>>>(1);                   // best3
    kern_take<<<1, 1024>>>(1, 0, out);             // take3
    kern_bestG<<<128, 256>>>(0);                   // best4
    kern_take<<<1, 1024>>>(0, 1, out);             // take4
    kern_bestG<<<128, 256>>>(1);                   // best5
    kern_take<<<1, 1024>>>(1, 0, out);             // take5
    kern_bestG<<<128, 256>>>(0);                   // best6

    kern_finish<<<1, 1024, CAP * CAP * (int)sizeof(float)>>>(0, out);  // tail (n ~140)
}